// round 11
// baseline (speedup 1.0000x reference)
#include <cuda_runtime.h>
#include <math.h>

#define DIMK 512
#define HD   1024

typedef unsigned long long ull;

// 4-way k-split partials (chunk c covers k in [c*128, c*128+128))
__device__ __align__(16) float g_caus4[4 * 64 * HD];
__device__ __align__(16) float g_eff4 [4 * 64 * HD];
__device__ __align__(16) float g_ctxT4[4 * HD * 64];   // transposed [h][b]
// reduced buffers
__device__ __align__(16) float g_caus[64 * HD];        // includes +b1
__device__ __align__(16) float g_eff [64 * HD];
__device__ __align__(16) float g_ctxT[HD * 64];
// separable linear parts (w' = 0.5*W2)
__device__ float g_A[64];
__device__ float g_B[64];
__device__ float g_C[64];

// ---------------------------------------------------------------------------
// Phase 1: three 64x512 @ 512x1024 GEMMs. grid=(128,3): x>>2 = 32-col tile,
// x&3 = k-chunk (128). Both X and W tiles staged in smem. 384 blocks.
// ---------------------------------------------------------------------------
__global__ void __launch_bounds__(256) gemm_kernel(
    const float* __restrict__ state, const float* __restrict__ action,
    const float* __restrict__ embed, const float* __restrict__ W1)
{
    const int slot    = blockIdx.y;
    const int colbase = (blockIdx.x >> 2) * 32;
    const int chunk   = blockIdx.x & 3;
    const int kbase   = chunk * 128;

    const float* W = W1 + slot * DIMK * HD;

    __shared__ float Xs[64][128];   // 32 KB
    __shared__ float Ws[128][32];   // 16 KB

    const int tid = threadIdx.x;
    const int tx  = tid & 15;
    const int ty  = tid >> 4;

    for (int idx = tid; idx < 2048; idx += 256) {
        int row = idx >> 5, q = idx & 31;
        int gc  = kbase + q * 4;
        float4 v;
        if (slot < 2) {
            v = *reinterpret_cast<const float4*>(embed + row * DIMK + gc);
        } else {
            float4 s4 = *reinterpret_cast<const float4*>(state  + row * DIMK + gc);
            float4 a4 = *reinterpret_cast<const float4*>(action + row * DIMK + gc);
            v = make_float4(s4.x + a4.x, s4.y + a4.y, s4.z + a4.z, s4.w + a4.w);
        }
        *reinterpret_cast<float4*>(&Xs[row][q * 4]) = v;
    }
    for (int idx = tid; idx < 1024; idx += 256) {
        int k = idx >> 3, c4 = idx & 7;
        *reinterpret_cast<float4*>(&Ws[k][4 * c4]) =
            *reinterpret_cast<const float4*>(W + (kbase + k) * HD + colbase + 4 * c4);
    }
    __syncthreads();

    float acc[4][2] = {};
    #pragma unroll 8
    for (int k = 0; k < 128; k++) {
        float2 w = *reinterpret_cast<const float2*>(&Ws[k][2 * tx]);
        #pragma unroll
        for (int r = 0; r < 4; r++) {
            float xv = Xs[ty + 16 * r][k];
            acc[r][0] = fmaf(xv, w.x, acc[r][0]);
            acc[r][1] = fmaf(xv, w.y, acc[r][1]);
        }
    }

    #pragma unroll
    for (int r = 0; r < 4; r++) {
        int row = ty + 16 * r;
        int c0  = colbase + 2 * tx;
        if (slot == 0) {
            float* dst = g_caus4 + chunk * 64 * HD;
            dst[row * HD + c0]     = acc[r][0];
            dst[row * HD + c0 + 1] = acc[r][1];
        } else if (slot == 1) {
            float* dst = g_eff4 + chunk * 64 * HD;
            dst[row * HD + c0]     = acc[r][0];
            dst[row * HD + c0 + 1] = acc[r][1];
        } else {
            float* dst = g_ctxT4 + chunk * HD * 64;
            dst[c0 * 64 + row]       = acc[r][0];
            dst[(c0 + 1) * 64 + row] = acc[r][1];
        }
    }
}

// ---------------------------------------------------------------------------
// Phase 1.25: reduce 4 partials -> single buffers (b1 folded into caus).
// ---------------------------------------------------------------------------
__global__ void __launch_bounds__(256) reduce_kernel(const float* __restrict__ b1)
{
    const int slot = blockIdx.x >> 6;
    const int gidx = (blockIdx.x & 63) * 256 + threadIdx.x;
    const int N = 64 * HD / 4;
    if (gidx >= N) return;

    const float4* s0; float4* dst;
    if (slot == 0)      { s0 = (const float4*)g_caus4; dst = (float4*)g_caus; }
    else if (slot == 1) { s0 = (const float4*)g_eff4;  dst = (float4*)g_eff;  }
    else                { s0 = (const float4*)g_ctxT4; dst = (float4*)g_ctxT; }
    const float4* s1 = s0 + N; const float4* s2 = s0 + 2 * N; const float4* s3 = s0 + 3 * N;

    float4 a = s0[gidx], b = s1[gidx], c = s2[gidx], d = s3[gidx];
    float4 r = make_float4(a.x + b.x + c.x + d.x, a.y + b.y + c.y + d.y,
                           a.z + b.z + c.z + d.z, a.w + b.w + c.w + d.w);
    if (slot == 0) {
        float4 bb = *reinterpret_cast<const float4*>(b1 + ((gidx * 4) & (HD - 1)));
        r.x += bb.x; r.y += bb.y; r.z += bb.z; r.w += bb.w;
    }
    dst[gidx] = r;
}

// ---------------------------------------------------------------------------
// Phase 1.5: separable linear parts A_i, B_j, C_b  (w' = 0.5*W2)
// ---------------------------------------------------------------------------
__global__ void __launch_bounds__(256) pre_kernel(const float* __restrict__ W2)
{
    const int slot = blockIdx.x;
    const int tid  = threadIdx.x;
    if (slot < 2) {
        const float* P = slot == 0 ? g_caus : g_eff;
        float* dst = slot == 0 ? g_A : g_B;
        int w = tid >> 5, lane = tid & 31;
        #pragma unroll
        for (int m = 0; m < 8; m++) {
            int row = w * 8 + m;
            float s = 0.f;
            for (int h = lane; h < HD; h += 32)
                s += P[row * HD + h] * (0.5f * W2[h]);
            #pragma unroll
            for (int off = 16; off; off >>= 1)
                s += __shfl_down_sync(0xffffffffu, s, off);
            if (lane == 0) dst[row] = s;
        }
    } else {
        __shared__ float red[256];
        int b = tid & 63, part = tid >> 6;
        float s = 0.f;
        for (int h = part * 256; h < part * 256 + 256; h++)
            s += g_ctxT[h * 64 + b] * (0.5f * W2[h]);
        red[tid] = s;
        __syncthreads();
        if (tid < 64)
            g_C[tid] = red[tid] + red[tid + 64] + red[tid + 128] + red[tid + 192];
    }
}

// ---------------------------------------------------------------------------
// f32x2 packed helpers
// ---------------------------------------------------------------------------
__device__ __forceinline__ ull pack2(float a, float b) {
    ull r;
    asm("mov.b64 %0, {%1, %2};" : "=l"(r)
        : "r"(__float_as_uint(a)), "r"(__float_as_uint(b)));
    return r;
}
__device__ __forceinline__ void unpack2(ull v, float& a, float& b) {
    unsigned int x, y;
    asm("mov.b64 {%0, %1}, %2;" : "=r"(x), "=r"(y) : "l"(v));
    a = __uint_as_float(x); b = __uint_as_float(y);
}
__device__ __forceinline__ ull add2(ull a, ull b) {
    ull r; asm("add.rn.f32x2 %0, %1, %2;" : "=l"(r) : "l"(a), "l"(b)); return r;
}
__device__ __forceinline__ ull mul2(ull a, ull b) {
    ull r; asm("mul.rn.f32x2 %0, %1, %2;" : "=l"(r) : "l"(a), "l"(b)); return r;
}
__device__ __forceinline__ ull fma2(ull a, ull b, ull c) {
    ull r; asm("fma.rn.f32x2 %0, %1, %2, %3;" : "=l"(r) : "l"(a), "l"(b), "l"(c)); return r;
}
__device__ __forceinline__ float tanh_ap(float x) {
    float r; asm("tanh.approx.f32 %0, %1;" : "=f"(r) : "f"(x)); return r;
}

// ---------------------------------------------------------------------------
// Phase 2: logit = (A_i + B_j + C_b + b2) + sum_h xw'*tanh(...)
// 6 f32x2 + 2 tanh per lane-k, DUAL accumulators, 8k scheduled body,
// 64-reg budget (__launch_bounds__(256,4)) for deep ILP.
// ---------------------------------------------------------------------------
__global__ void __launch_bounds__(256, 4) score_kernel(
    const float* __restrict__ W2, const float* __restrict__ b2,
    float* __restrict__ out)
{
    extern __shared__ float sm[];
    float* caus_s = sm;              // 2 * 1024
    float* eff_s  = sm + 2048;       // 4 * 1024
    float* w2p    = sm + 6144;       // 2048 (1024 pairs of 0.5*W2, duplicated)
    float* ctx_s  = sm + 8192;       // 64 * 64

    const int tid = threadIdx.x;
    const int i0  = (blockIdx.x >> 4) * 2;
    const int j0  = (blockIdx.x & 15) * 4;

    for (int lin = tid; lin < 2048; lin += 256) {
        int r = lin >> 10, c = lin & 1023;
        caus_s[lin] = g_caus[(i0 + r) * HD + c];
    }
    for (int lin = tid; lin < 4096; lin += 256) {
        int r = lin >> 10, c = lin & 1023;
        eff_s[lin]  = g_eff[(j0 + r) * HD + c];
    }
    for (int lin = tid; lin < 1024; lin += 256) {
        float v = 0.5f * W2[lin];
        w2p[2 * lin]     = v;
        w2p[2 * lin + 1] = v;
    }

    const int w    = tid >> 5;
    const int lane = tid & 31;
    const int wi   = w >> 2, wj = w & 3;
    const float* cs = caus_s + wi * 1024;
    const float* es = eff_s  + wj * 1024;
    const ull*  ctxp = reinterpret_cast<const ull*>(ctx_s);

    const ull C0 = pack2(0.7978845608f, 0.7978845608f);
    const ull C1 = pack2(0.0356774081f, 0.0356774081f);
    ull acc0 = pack2(0.f, 0.f);
    ull acc1 = pack2(0.f, 0.f);

    for (int ht = 0; ht < HD; ht += 64) {
        __syncthreads();
        for (int lin = tid * 4; lin < 64 * 64; lin += 256 * 4) {
            *reinterpret_cast<float4*>(ctx_s + lin) =
                *reinterpret_cast<const float4*>(g_ctxT + ht * 64 + lin);
        }
        __syncthreads();

        const float* w2row = w2p + 2 * ht;
        #pragma unroll 2
        for (int k = 0; k < 64; k += 4) {
            // batched loads for 4 k's
            float4 cv = *reinterpret_cast<const float4*>(cs + ht + k);
            float4 ev = *reinterpret_cast<const float4*>(es + ht + k);
            ull hw[4], cc[4];
            #pragma unroll
            for (int q = 0; q < 4; q++) {
                hw[q] = *reinterpret_cast<const ull*>(w2row + 2 * (k + q));
                cc[q] = ctxp[(k + q) * 32 + lane];
            }
            float ce[4] = {cv.x + ev.x, cv.y + ev.y, cv.z + ev.z, cv.w + ev.w};
            #pragma unroll
            for (int q = 0; q < 4; q++) {
                ull ce2 = pack2(ce[q], ce[q]);
                ull x2  = add2(ce2, cc[q]);
                ull u2  = mul2(x2, x2);
                ull p2  = fma2(u2, C1, C0);
                ull in2 = mul2(x2, p2);
                float ia, ib; unpack2(in2, ia, ib);
                ull t2  = pack2(tanh_ap(ia), tanh_ap(ib));
                ull xw2 = mul2(x2, hw[q]);
                if (q & 1) acc1 = fma2(xw2, t2, acc1);
                else       acc0 = fma2(xw2, t2, acc0);
            }
        }
    }

    ull acc = add2(acc0, acc1);
    float a0, a1; unpack2(acc, a0, a1);
    float base = g_A[i0 + wi] + g_B[j0 + wj] + b2[0];
    float2 cb = *reinterpret_cast<const float2*>(g_C + 2 * lane);
    float s = 1.0f / (1.0f + expf(-(a0 + base + cb.x)))
            + 1.0f / (1.0f + expf(-(a1 + base + cb.y)));
    #pragma unroll
    for (int off = 16; off; off >>= 1)
        s += __shfl_down_sync(0xffffffffu, s, off);
    if (lane == 0)
        out[(i0 + wi) * 64 + (j0 + wj)] = s * (1.0f / 64.0f);
}

// ---------------------------------------------------------------------------
extern "C" void kernel_launch(void* const* d_in, const int* in_sizes, int n_in,
                              void* d_out, int out_size)
{
    const float* state  = (const float*)d_in[0];
    const float* action = (const float*)d_in[1];
    const float* embed  = (const float*)d_in[2];
    const float* W1     = (const float*)d_in[3];
    const float* b1     = (const float*)d_in[4];
    const float* W2     = (const float*)d_in[5];
    const float* b2     = (const float*)d_in[6];
    float* out = (float*)d_out;

    dim3 g1(128, 3);
    gemm_kernel<<<g1, 256>>>(state, action, embed, W1);
    reduce_kernel<<<192, 256>>>(b1);
    pre_kernel<<<3, 256>>>(W2);

    const int smem = (2048 + 4096 + 2048 + 4096) * sizeof(float); // 49152 B
    cudaFuncSetAttribute(score_kernel, cudaFuncAttributeMaxDynamicSharedMemorySize, smem);
    score_kernel<<<512, 256, smem>>>(W2, b2, out);
}

// round 15
// speedup vs baseline: 1.6365x; 1.6365x over previous
#include <cuda_runtime.h>
#include <math.h>

#define DIMK 512
#define HD   1024

typedef unsigned long long ull;

// 4-way k-split partials (chunk c covers k in [c*128, c*128+128))
__device__ __align__(16) float g_caus4[4 * 64 * HD];
__device__ __align__(16) float g_eff4 [4 * 64 * HD];
__device__ __align__(16) float g_ctxT4[4 * HD * 64];   // transposed [h][b]
// reduced buffers
__device__ __align__(16) float g_caus[64 * HD];        // includes +b1
__device__ __align__(16) float g_eff [64 * HD];
__device__ __align__(16) float g_ctxT[HD * 64];
// separable linear parts (w' = 0.5*W2)
__device__ float g_A[64];
__device__ float g_B[64];
__device__ float g_C[64];

// ---------------------------------------------------------------------------
// Phase 1: three 64x512 @ 512x1024 GEMMs. grid=(128,3). (unchanged from R10)
// ---------------------------------------------------------------------------
__global__ void __launch_bounds__(256) gemm_kernel(
    const float* __restrict__ state, const float* __restrict__ action,
    const float* __restrict__ embed, const float* __restrict__ W1)
{
    const int slot    = blockIdx.y;
    const int colbase = (blockIdx.x >> 2) * 32;
    const int chunk   = blockIdx.x & 3;
    const int kbase   = chunk * 128;

    const float* W = W1 + slot * DIMK * HD;

    __shared__ float Xs[64][128];
    __shared__ float Ws[128][32];

    const int tid = threadIdx.x;
    const int tx  = tid & 15;
    const int ty  = tid >> 4;

    for (int idx = tid; idx < 2048; idx += 256) {
        int row = idx >> 5, q = idx & 31;
        int gc  = kbase + q * 4;
        float4 v;
        if (slot < 2) {
            v = *reinterpret_cast<const float4*>(embed + row * DIMK + gc);
        } else {
            float4 s4 = *reinterpret_cast<const float4*>(state  + row * DIMK + gc);
            float4 a4 = *reinterpret_cast<const float4*>(action + row * DIMK + gc);
            v = make_float4(s4.x + a4.x, s4.y + a4.y, s4.z + a4.z, s4.w + a4.w);
        }
        *reinterpret_cast<float4*>(&Xs[row][q * 4]) = v;
    }
    for (int idx = tid; idx < 1024; idx += 256) {
        int k = idx >> 3, c4 = idx & 7;
        *reinterpret_cast<float4*>(&Ws[k][4 * c4]) =
            *reinterpret_cast<const float4*>(W + (kbase + k) * HD + colbase + 4 * c4);
    }
    __syncthreads();

    float acc[4][2] = {};
    #pragma unroll 8
    for (int k = 0; k < 128; k++) {
        float2 w = *reinterpret_cast<const float2*>(&Ws[k][2 * tx]);
        #pragma unroll
        for (int r = 0; r < 4; r++) {
            float xv = Xs[ty + 16 * r][k];
            acc[r][0] = fmaf(xv, w.x, acc[r][0]);
            acc[r][1] = fmaf(xv, w.y, acc[r][1]);
        }
    }

    #pragma unroll
    for (int r = 0; r < 4; r++) {
        int row = ty + 16 * r;
        int c0  = colbase + 2 * tx;
        if (slot == 0) {
            float* dst = g_caus4 + chunk * 64 * HD;
            dst[row * HD + c0]     = acc[r][0];
            dst[row * HD + c0 + 1] = acc[r][1];
        } else if (slot == 1) {
            float* dst = g_eff4 + chunk * 64 * HD;
            dst[row * HD + c0]     = acc[r][0];
            dst[row * HD + c0 + 1] = acc[r][1];
        } else {
            float* dst = g_ctxT4 + chunk * HD * 64;
            dst[c0 * 64 + row]       = acc[r][0];
            dst[(c0 + 1) * 64 + row] = acc[r][1];
        }
    }
}

// ---------------------------------------------------------------------------
// Phase 1.25: reduce 4 partials (unchanged)
// ---------------------------------------------------------------------------
__global__ void __launch_bounds__(256) reduce_kernel(const float* __restrict__ b1)
{
    const int slot = blockIdx.x >> 6;
    const int gidx = (blockIdx.x & 63) * 256 + threadIdx.x;
    const int N = 64 * HD / 4;
    if (gidx >= N) return;

    const float4* s0; float4* dst;
    if (slot == 0)      { s0 = (const float4*)g_caus4; dst = (float4*)g_caus; }
    else if (slot == 1) { s0 = (const float4*)g_eff4;  dst = (float4*)g_eff;  }
    else                { s0 = (const float4*)g_ctxT4; dst = (float4*)g_ctxT; }
    const float4* s1 = s0 + N; const float4* s2 = s0 + 2 * N; const float4* s3 = s0 + 3 * N;

    float4 a = s0[gidx], b = s1[gidx], c = s2[gidx], d = s3[gidx];
    float4 r = make_float4(a.x + b.x + c.x + d.x, a.y + b.y + c.y + d.y,
                           a.z + b.z + c.z + d.z, a.w + b.w + c.w + d.w);
    if (slot == 0) {
        float4 bb = *reinterpret_cast<const float4*>(b1 + ((gidx * 4) & (HD - 1)));
        r.x += bb.x; r.y += bb.y; r.z += bb.z; r.w += bb.w;
    }
    dst[gidx] = r;
}

// ---------------------------------------------------------------------------
// Phase 1.5: separable linear parts (unchanged)
// ---------------------------------------------------------------------------
__global__ void __launch_bounds__(256) pre_kernel(const float* __restrict__ W2)
{
    const int slot = blockIdx.x;
    const int tid  = threadIdx.x;
    if (slot < 2) {
        const float* P = slot == 0 ? g_caus : g_eff;
        float* dst = slot == 0 ? g_A : g_B;
        int w = tid >> 5, lane = tid & 31;
        #pragma unroll
        for (int m = 0; m < 8; m++) {
            int row = w * 8 + m;
            float s = 0.f;
            for (int h = lane; h < HD; h += 32)
                s += P[row * HD + h] * (0.5f * W2[h]);
            #pragma unroll
            for (int off = 16; off; off >>= 1)
                s += __shfl_down_sync(0xffffffffu, s, off);
            if (lane == 0) dst[row] = s;
        }
    } else {
        __shared__ float red[256];
        int b = tid & 63, part = tid >> 6;
        float s = 0.f;
        for (int h = part * 256; h < part * 256 + 256; h++)
            s += g_ctxT[h * 64 + b] * (0.5f * W2[h]);
        red[tid] = s;
        __syncthreads();
        if (tid < 64)
            g_C[tid] = red[tid] + red[tid + 64] + red[tid + 128] + red[tid + 192];
    }
}

// ---------------------------------------------------------------------------
// f32x2 packed helpers
// ---------------------------------------------------------------------------
__device__ __forceinline__ ull pack2(float a, float b) {
    ull r;
    asm("mov.b64 %0, {%1, %2};" : "=l"(r)
        : "r"(__float_as_uint(a)), "r"(__float_as_uint(b)));
    return r;
}
__device__ __forceinline__ void unpack2(ull v, float& a, float& b) {
    unsigned int x, y;
    asm("mov.b64 {%0, %1}, %2;" : "=r"(x), "=r"(y) : "l"(v));
    a = __uint_as_float(x); b = __uint_as_float(y);
}
__device__ __forceinline__ ull add2(ull a, ull b) {
    ull r; asm("add.rn.f32x2 %0, %1, %2;" : "=l"(r) : "l"(a), "l"(b)); return r;
}
__device__ __forceinline__ ull mul2(ull a, ull b) {
    ull r; asm("mul.rn.f32x2 %0, %1, %2;" : "=l"(r) : "l"(a), "l"(b)); return r;
}
__device__ __forceinline__ ull fma2(ull a, ull b, ull c) {
    ull r; asm("fma.rn.f32x2 %0, %1, %2, %3;" : "=l"(r) : "l"(a), "l"(b), "l"(c)); return r;
}
__device__ __forceinline__ float tanh_ap(float x) {
    float r; asm("tanh.approx.f32 %0, %1;" : "=f"(r) : "f"(x)); return r;
}

// ---------------------------------------------------------------------------
// Phase 2: each warp handles TWO (i,j) pairs sharing i (shared cs/ctx/w2
// loads, two independent dependency chains). 128 threads = 4 warps = 2i x 4j
// tile; grid = 512 (balanced single wave). Default launch bounds (R11 lesson).
// ---------------------------------------------------------------------------
__global__ void __launch_bounds__(128) score_kernel(
    const float* __restrict__ W2, const float* __restrict__ b2,
    float* __restrict__ out)
{
    extern __shared__ float sm[];
    float* caus_s = sm;              // 2 * 1024
    float* eff_s  = sm + 2048;       // 4 * 1024
    float* w2p    = sm + 6144;       // 2048 (1024 pairs of 0.5*W2, duplicated)
    float* ctx_s  = sm + 8192;       // 64 * 64

    const int tid = threadIdx.x;
    const int i0  = (blockIdx.x >> 4) * 2;
    const int j0  = (blockIdx.x & 15) * 4;

    for (int lin = tid; lin < 2048; lin += 128) {
        int r = lin >> 10, c = lin & 1023;
        caus_s[lin] = g_caus[(i0 + r) * HD + c];
    }
    for (int lin = tid; lin < 4096; lin += 128) {
        int r = lin >> 10, c = lin & 1023;
        eff_s[lin]  = g_eff[(j0 + r) * HD + c];
    }
    for (int lin = tid; lin < 1024; lin += 128) {
        float v = 0.5f * W2[lin];
        w2p[2 * lin]     = v;
        w2p[2 * lin + 1] = v;
    }

    const int w    = tid >> 5;
    const int lane = tid & 31;
    const int wi   = w >> 1;          // 0..1
    const int wjb  = (w & 1) * 2;     // 0 or 2; warp handles j = wjb, wjb+1
    const float* cs = caus_s + wi * 1024;
    const float* e0 = eff_s + wjb * 1024;
    const float* e1 = eff_s + (wjb + 1) * 1024;
    const ull*  ctxp = reinterpret_cast<const ull*>(ctx_s);

    const ull C0 = pack2(0.7978845608f, 0.7978845608f);
    const ull C1 = pack2(0.0356774081f, 0.0356774081f);
    ull accA = pack2(0.f, 0.f);       // pair (wi, wjb)
    ull accB = pack2(0.f, 0.f);       // pair (wi, wjb+1)

    for (int ht = 0; ht < HD; ht += 64) {
        __syncthreads();
        for (int lin = tid * 4; lin < 64 * 64; lin += 128 * 4) {
            *reinterpret_cast<float4*>(ctx_s + lin) =
                *reinterpret_cast<const float4*>(g_ctxT + ht * 64 + lin);
        }
        __syncthreads();

        const float* w2row = w2p + 2 * ht;
        #pragma unroll 4
        for (int k = 0; k < 64; k += 4) {
            float4 cv  = *reinterpret_cast<const float4*>(cs + ht + k);
            float4 ev0 = *reinterpret_cast<const float4*>(e0 + ht + k);
            float4 ev1 = *reinterpret_cast<const float4*>(e1 + ht + k);
            float ceA[4] = {cv.x + ev0.x, cv.y + ev0.y, cv.z + ev0.z, cv.w + ev0.w};
            float ceB[4] = {cv.x + ev1.x, cv.y + ev1.y, cv.z + ev1.z, cv.w + ev1.w};
            #pragma unroll
            for (int q = 0; q < 4; q++) {
                ull hw2 = *reinterpret_cast<const ull*>(w2row + 2 * (k + q));
                ull c2  = ctxp[(k + q) * 32 + lane];
                // chain A
                ull xA  = add2(pack2(ceA[q], ceA[q]), c2);
                ull uA  = mul2(xA, xA);
                ull pA  = fma2(uA, C1, C0);
                ull inA = mul2(xA, pA);
                float iaA, ibA; unpack2(inA, iaA, ibA);
                ull tA  = pack2(tanh_ap(iaA), tanh_ap(ibA));
                ull xwA = mul2(xA, hw2);
                accA = fma2(xwA, tA, accA);
                // chain B (independent)
                ull xB  = add2(pack2(ceB[q], ceB[q]), c2);
                ull uB  = mul2(xB, xB);
                ull pB  = fma2(uB, C1, C0);
                ull inB = mul2(xB, pB);
                float iaB, ibB; unpack2(inB, iaB, ibB);
                ull tB  = pack2(tanh_ap(iaB), tanh_ap(ibB));
                ull xwB = mul2(xB, hw2);
                accB = fma2(xwB, tB, accB);
            }
        }
    }

    float2 cb = *reinterpret_cast<const float2*>(g_C + 2 * lane);
    float baseA = g_A[i0 + wi] + g_B[j0 + wjb] + b2[0];
    float baseB = g_A[i0 + wi] + g_B[j0 + wjb + 1] + b2[0];

    float a0, a1; unpack2(accA, a0, a1);
    float sA = 1.0f / (1.0f + expf(-(a0 + baseA + cb.x)))
             + 1.0f / (1.0f + expf(-(a1 + baseA + cb.y)));
    float b0, b1v; unpack2(accB, b0, b1v);
    float sB = 1.0f / (1.0f + expf(-(b0 + baseB + cb.x)))
             + 1.0f / (1.0f + expf(-(b1v + baseB + cb.y)));
    #pragma unroll
    for (int off = 16; off; off >>= 1) {
        sA += __shfl_down_sync(0xffffffffu, sA, off);
        sB += __shfl_down_sync(0xffffffffu, sB, off);
    }
    if (lane == 0) {
        out[(i0 + wi) * 64 + (j0 + wjb)]     = sA * (1.0f / 64.0f);
        out[(i0 + wi) * 64 + (j0 + wjb + 1)] = sB * (1.0f / 64.0f);
    }
}

// ---------------------------------------------------------------------------
extern "C" void kernel_launch(void* const* d_in, const int* in_sizes, int n_in,
                              void* d_out, int out_size)
{
    const float* state  = (const float*)d_in[0];
    const float* action = (const float*)d_in[1];
    const float* embed  = (const float*)d_in[2];
    const float* W1     = (const float*)d_in[3];
    const float* b1     = (const float*)d_in[4];
    const float* W2     = (const float*)d_in[5];
    const float* b2     = (const float*)d_in[6];
    float* out = (float*)d_out;

    dim3 g1(128, 3);
    gemm_kernel<<<g1, 256>>>(state, action, embed, W1);
    reduce_kernel<<<192, 256>>>(b1);
    pre_kernel<<<3, 256>>>(W2);

    const int smem = (2048 + 4096 + 2048 + 4096) * sizeof(float); // 49152 B
    cudaFuncSetAttribute(score_kernel, cudaFuncAttributeMaxDynamicSharedMemorySize, smem);
    score_kernel<<<512, 128, smem>>>(W2, b2, out);
}